// round 13
// baseline (speedup 1.0000x reference)
#include <cuda_runtime.h>

#define Bc 8
#define Hc 320
#define Wc 1024
#define WW 32                    // 32-bit words per row
#define NPIX (Bc*Hc*Wc)          // 2621440
#define NWORD (NPIX/32)
#define TLX 32
#define TLY 64
#define CAP 768
#define HROWS 104                // halo rows per tile: [y0-20, y0+83]
#define KP2ROWS 55               // padded pair-table rows: mp in [0,54]

// Static device scratch (no allocations)
__device__ unsigned g_srcm[NWORD];
__device__ unsigned g_dstm[NWORD];
__device__ unsigned g_mask[NWORD];     // found bitmask
__device__ float2   g_v[NPIX];         // (vx,vy), sparse at found px
__device__ float2   g_K2[KP2ROWS*41];  // P2[mp] = (K[mp-7], K[mp-8])
__device__ int      g_rank[7*15];      // argsort-order rank of each (dy,dx)

// ---- f32x2 helpers -------------------------------------------------------
__device__ __forceinline__ unsigned long long f2u(float a, float b) {
    unsigned long long r;
    asm("mov.b64 %0, {%1,%2};" : "=l"(r) : "f"(a), "f"(b));
    return r;
}
__device__ __forceinline__ float2 u2f(unsigned long long v) {
    float2 r;
    asm("mov.b64 {%0,%1}, %2;" : "=f"(r.x), "=f"(r.y) : "l"(v));
    return r;
}
__device__ __forceinline__ void fma2(unsigned long long& acc,
                                     unsigned long long a,
                                     unsigned long long b) {
    asm("fma.rn.f32x2 %0, %1, %2, %0;" : "+l"(acc) : "l"(a), "l"(b));
}
__device__ __forceinline__ float frcp(float x) {
    float r;
    asm("rcp.approx.ftz.f32 %0, %1;" : "=f"(r) : "f"(x));
    return r;
}

__device__ __forceinline__ float kc(int m, int dx) {   // kernel row value
    if (m < 0 || m > 40) return 0.f;
    int dy = m - 20;
    return 0.7f * expf(-sqrtf((float)(dx*dx + dy*dy)) * (1.9f/24.f));
}

// ---------------------------------------------------------------------------
// Kernel 0: bitmasks, 16 px/thread (4x LDG.128 per map, single wave)
//           + fused LUT build (pair K-table + rank).
// ---------------------------------------------------------------------------
__global__ void __launch_bounds__(256) bitmask_kernel(
    const float4* __restrict__ src4, const float4* __restrict__ dst4,
    const float* __restrict__ xx,    const float* __restrict__ yy)
{
    int t    = blockIdx.x * 256 + threadIdx.x;    // NPIX/16 threads
    int sub  = threadIdx.x & 1;                   // 2 threads per mask word

    unsigned ns = 0, nd = 0;
    #pragma unroll
    for (int q = 0; q < 4; q++) {
        float4 s = src4[4*t + q];
        ns |= ((unsigned)(s.x > 0.5f)        | ((unsigned)(s.y > 0.5f) << 1) |
               ((unsigned)(s.z > 0.5f) << 2) | ((unsigned)(s.w > 0.5f) << 3)) << (q*4);
    }
    #pragma unroll
    for (int q = 0; q < 4; q++) {
        float4 d = dst4[4*t + q];
        nd |= ((unsigned)(d.x > 0.5f)        | ((unsigned)(d.y > 0.5f) << 1) |
               ((unsigned)(d.z > 0.5f) << 2) | ((unsigned)(d.w > 0.5f) << 3)) << (q*4);
    }
    unsigned vs = ns << (sub * 16);
    unsigned vd = nd << (sub * 16);
    vs |= __shfl_xor_sync(0xFFFFFFFFu, vs, 1);
    vd |= __shfl_xor_sync(0xFFFFFFFFu, vd, 1);
    if (sub == 0) { g_srcm[t >> 1] = vs; g_dstm[t >> 1] = vd; }

    if (blockIdx.x < 9) {                          // one-shot LUT build
        int i = blockIdx.x * 256 + threadIdx.x;
        if (i < KP2ROWS*41) {
            int mp = i / 41, dx = i % 41 - 20;
            g_K2[i] = make_float2(kc(mp - 7, dx), kc(mp - 8, dx));
        }
        if (i < 105) {
            int dx = (int)xx[i], dy = (int)yy[i];
            g_rank[(dy + 3)*15 + (dx + 7)] = i;    // exact argsort order
        }
    }
}

// ---------------------------------------------------------------------------
// 15/5-bit neighborhood window extraction from 3 mask words.
// ---------------------------------------------------------------------------
__device__ __forceinline__ unsigned win_extract(
    unsigned l, unsigned m, unsigned r, int j, int radius)
{
    if (j < 16) {
        unsigned long long lm = ((unsigned long long)m << 32) | l;
        return (unsigned)(lm >> (32 + j - radius));
    } else {
        unsigned long long mr = ((unsigned long long)r << 32) | m;
        return (unsigned)(mr >> (j - radius));
    }
}

// ---------------------------------------------------------------------------
// Kernel 1: sparsity filter + nearest-correspondence (bitmask windows).
// ---------------------------------------------------------------------------
__global__ void __launch_bounds__(256) match_kernel()
{
    __shared__ int s_rank[7*15];
    if (threadIdx.x < 105) s_rank[threadIdx.x] = g_rank[threadIdx.x];
    __syncthreads();

    int gid = blockIdx.x * 256 + threadIdx.x;
    int j   = gid & 31;
    int wi  = gid >> 5;

    unsigned own = g_srcm[wi];
    if (own == 0) {                          // early-out (~52% of warps)
        if (j == 0) g_mask[wi] = 0;
        return;
    }

    int wx  = wi & (WW - 1);
    int yb  = wi >> 5;
    int y   = yb % Hc;
    int b   = yb / Hc;

    unsigned sw[3][3];
    #pragma unroll
    for (int r = 0; r < 3; r++) {
        int ry = y - 2 + r;
        #pragma unroll
        for (int c = 0; c < 3; c++) {
            int rc = wx - 1 + c;
            unsigned v = 0;
            if ((unsigned)ry < (unsigned)Hc && (unsigned)rc < (unsigned)WW)
                v = g_srcm[(b*Hc + ry)*WW + rc];
            sw[r][c] = v;
        }
    }
    bool active = (own >> j) & 1u;
    unsigned h0 = win_extract(sw[0][0], sw[0][1], sw[0][2], j, 2) & 31u;
    unsigned h1 = win_extract(sw[1][0], sw[1][1], sw[1][2], j, 2) & 31u;
    unsigned h2 = win_extract(sw[2][0], sw[2][1], sw[2][2], j, 2) & 3u;
    bool kept = active && !(h0 | h1 | h2);

    bool found = false;
    float vx = 0.f, vy = 0.f;
    if (__ballot_sync(0xFFFFFFFFu, kept)) {
        int bestkey = 1 << 30, bdx = 0, bdy = 0;
        #pragma unroll
        for (int r = 0; r < 7; r++) {
            int dy = r - 3;
            int ry = y + dy;
            unsigned l = 0, m = 0, rr = 0;
            if ((unsigned)ry < (unsigned)Hc) {
                int base = (b*Hc + ry)*WW;
                if (wx > 0)      l  = g_dstm[base + wx - 1];
                m = g_dstm[base + wx];
                if (wx < WW - 1) rr = g_dstm[base + wx + 1];
            }
            if (kept) {
                unsigned win = win_extract(l, m, rr, j, 7) & 0x7FFFu;
                while (win) {
                    int k = __ffs(win) - 1; win &= win - 1;
                    int key = s_rank[r*15 + k];
                    if (key < bestkey) { bestkey = key; bdx = k - 7; bdy = dy; }
                }
            }
        }
        if (kept && bestkey < (1 << 30)) {
            found = true; vx = (float)bdx; vy = (float)bdy;
        }
    }

    unsigned fb = __ballot_sync(0xFFFFFFFFu, found);
    if (j == 0) g_mask[wi] = fb;
    if (found)  g_v[gid] = make_float2(vx, vy);
}

// ---------------------------------------------------------------------------
// Kernel 2: sparse splat-as-gather, 32x64 tile, 8 rows/thread,
// row-bucketed CSR, f32x2 packed pair taps. TWO tiles per block
// (batches z and z+4) — K table loads once, single clean wave.
// ---------------------------------------------------------------------------
__global__ void __launch_bounds__(256) splat_kernel(float* __restrict__ out)
{
    __shared__ float2   s_K2[KP2ROWS*41];
    __shared__ float4   s_pts[CAP];
    __shared__ int      s_rowcnt[HROWS];
    __shared__ int      s_rowofs[HROWS + 1];
    __shared__ unsigned s_tw[TLY];           // tile-row found words

    int tid  = threadIdx.x;
    int lane = tid & 31;
    int wrp  = tid >> 5;

    for (int i = tid; i < KP2ROWS*41; i += 256) s_K2[i] = g_K2[i];

    int x0 = blockIdx.x * TLX;
    int y0 = blockIdx.y * TLY;

    for (int half = 0; half < 2; half++) {
        int b = blockIdx.z + half * 4;

        if (tid < HROWS) s_rowcnt[tid] = 0;
        __syncthreads();

        // Phase A: load halo mask words (104 rows x 3 words), count per row.
        unsigned wrd[2]; int hrr[2], wjj[2], ofs[2];
        #pragma unroll
        for (int it = 0; it < 2; it++) {
            int t = tid + it*256;
            wrd[it] = 0; ofs[it] = 0; hrr[it] = 0; wjj[it] = 0;
            if (t < HROWS * 3) {
                int hr  = t / 3;
                int wi2 = t % 3 - 1;
                int ry  = y0 - 20 + hr;
                int wj  = (x0 >> 5) + wi2;
                hrr[it] = hr; wjj[it] = wj;
                if ((unsigned)ry < (unsigned)Hc && (unsigned)wj < (unsigned)WW) {
                    unsigned w = g_mask[(b*Hc + ry)*WW + wj];
                    if (wi2 == 0 && hr >= 20 && hr < 20 + TLY) s_tw[hr - 20] = w;
                    if (wi2 == -1) w &= 0xFFFFF000u;   // keep x >= x0-20
                    if (wi2 ==  1) w &= 0x000FFFFFu;   // keep x <= x0+51
                    wrd[it] = w;
                }
                if (wrd[it]) ofs[it] = atomicAdd(&s_rowcnt[hr], __popc(wrd[it]));
            }
        }
        __syncthreads();

        // Phase B: exclusive prefix sum over 104 row counts (warp 0).
        if (wrp == 0) {
            int carry = 0;
            #pragma unroll
            for (int c = 0; c < 4; c++) {
                int idx  = c*32 + lane;
                int vcnt = (idx < HROWS) ? s_rowcnt[idx] : 0;
                int inc  = vcnt;
                #pragma unroll
                for (int d = 1; d < 32; d <<= 1) {
                    int t2 = __shfl_up_sync(0xFFFFFFFFu, inc, d);
                    if (lane >= d) inc += t2;
                }
                if (idx <= HROWS) s_rowofs[idx] = inc - vcnt + carry;
                carry += __shfl_sync(0xFFFFFFFFu, inc, 31);
            }
            if (lane == 0) s_rowofs[HROWS] = carry;
        }
        __syncthreads();

        // Phase C: write points bucketed by halo row.
        #pragma unroll
        for (int it = 0; it < 2; it++) {
            if (wrd[it]) {
                int slot = s_rowofs[hrr[it]] + ofs[it];
                int ry   = y0 - 20 + hrr[it];
                unsigned w2 = wrd[it];
                while (w2) {
                    int jb = __ffs(w2) - 1; w2 &= w2 - 1;
                    int px = (wjj[it] << 5) + jb;
                    float2 v = g_v[(b*Hc + ry)*Wc + px];
                    if (slot < CAP)
                        s_pts[slot] = make_float4(__int_as_float(px - x0 + 20),
                                                  __int_as_float(hrr[it]),
                                                  v.x, v.y);
                    slot++;
                }
            }
        }
        __syncthreads();

        // Main loop: thread (g, tx) owns rows y0+8g..y0+8g+7 at col x0+tx.
        int tx = lane;
        int g8 = wrp * 8;
        int beg = min(s_rowofs[g8], CAP);
        int end = min(s_rowofs[min(g8 + 48, HROWS)], CAP);

        unsigned long long dd[4]  = {0,0,0,0};
        unsigned long long sxx[4] = {0,0,0,0};
        unsigned long long syy[4] = {0,0,0,0};
        const unsigned long long ones = f2u(1.f, 1.f);

        for (int i = beg; i < end; i++) {
            float4 p = s_pts[i];
            int u = __float_as_int(p.x) - tx;            // dx+20
            if ((unsigned)u <= 40u) {
                int base = (__float_as_int(p.y) - g8 + 7) * 41 + u;
                unsigned long long pz2 = f2u(p.z, p.z);
                unsigned long long pw2 = f2u(p.w, p.w);
                #pragma unroll
                for (int q = 0; q < 4; q++) {
                    unsigned long long w =
                        *reinterpret_cast<const unsigned long long*>(&s_K2[base - 82*q]);
                    fma2(dd[q],  w, ones);
                    fma2(sxx[q], w, pz2);
                    fma2(syy[q], w, pw2);
                }
            }
        }

        // Epilogue 1: morphed x/y.
        int x = x0 + tx;
        float fx = (float)x;
        #pragma unroll
        for (int q = 0; q < 4; q++) {
            float2 dq = u2f(dd[q]), xq = u2f(sxx[q]), yq = u2f(syy[q]);
            float den[2] = {dq.x, dq.y}, sx[2] = {xq.x, xq.y}, sy[2] = {yq.x, yq.y};
            #pragma unroll
            for (int h = 0; h < 2; h++) {
                int tr  = g8 + 2*q + h;
                int y   = y0 + tr;
                int idx = (b*Hc + y)*Wc + x;
                float rcp = frcp(den[h] + 1.6f);
                out[idx]        = fx + sx[h] * rcp;         // morphedx
                out[NPIX + idx] = (float)y + sy[h] * rcp;   // morphedy
            }
        }

        // Epilogue 2: channels 2..5 with float4 stores + zero fast path.
        {
            int c    = 2 + (lane >> 3);              // 2..5
            int grp  = lane & 7;
            int xg   = x0 + grp*4;
            bool usex = ((c & 1) == 0);              // ch2, ch4 use x-coord
            bool addv = (c >= 4);                    // ch4, ch5 add v
            float* obase = out + (size_t)c*NPIX + (b*Hc + (y0 + g8))*Wc + xg;
            int vbase = (b*Hc + (y0 + g8))*Wc + xg;
            #pragma unroll
            for (int rr = 0; rr < 8; rr++) {
                unsigned nib = (s_tw[g8 + rr] >> (grp*4)) & 0xFu;
                float4 val = make_float4(0.f, 0.f, 0.f, 0.f);
                if (nib) {
                    float fy = (float)(y0 + g8 + rr);
                    float vv[4];
                    #pragma unroll
                    for (int jj = 0; jj < 4; jj++) {
                        float r = 0.f;
                        if ((nib >> jj) & 1u) {
                            float base_c = usex ? (float)(xg + jj) : fy;
                            float add = 0.f;
                            if (addv) {
                                float2 gv = g_v[vbase + rr*Wc + jj];
                                add = usex ? gv.x : gv.y;
                            }
                            r = base_c + add;
                        }
                        vv[jj] = r;
                    }
                    val = make_float4(vv[0], vv[1], vv[2], vv[3]);
                }
                *reinterpret_cast<float4*>(obase + rr*Wc) = val;
            }
        }
        __syncthreads();   // tile done before reusing shared state
    }
}

extern "C" void kernel_launch(void* const* d_in, const int* in_sizes, int n_in,
                              void* d_out, int out_size)
{
    const float4* src4 = (const float4*)d_in[0];  // binMapsrc
    const float4* dst4 = (const float4*)d_in[1];  // binMapdst
    const float*  xx   = (const float*)d_in[2];
    const float*  yy   = (const float*)d_in[3];
    float* out = (float*)d_out;

    bitmask_kernel<<<NPIX/4096, 256>>>(src4, dst4, xx, yy);
    match_kernel<<<NPIX/256, 256>>>();

    dim3 grid(Wc/TLX, Hc/TLY, Bc/2);   // 32 x 5 x 4 = 640 blocks, 2 tiles each
    splat_kernel<<<grid, 256>>>(out);

    (void)in_sizes; (void)n_in; (void)out_size;
}

// round 14
// speedup vs baseline: 1.2573x; 1.2573x over previous
#include <cuda_runtime.h>

#define Bc 8
#define Hc 320
#define Wc 1024
#define WW 32                    // 32-bit words per row
#define NPIX (Bc*Hc*Wc)          // 2621440
#define NWORD (NPIX/32)
#define TLX 32
#define TLY 64
#define CAP 768
#define HROWS 104                // halo rows per tile: [y0-20, y0+83]
#define KP2ROWS 55               // padded pair-table rows: mp in [0,54]

// Static device scratch (no allocations)
__device__ unsigned g_srcm[NWORD];
__device__ unsigned g_dstm[NWORD];
__device__ unsigned g_mask[NWORD];     // found bitmask
__device__ float2   g_v[NPIX];         // (vx,vy), sparse at found px
__device__ float2   g_K2[KP2ROWS*41];  // P2[mp] = (K[mp-7], K[mp-8])
__device__ int      g_rank[7*15];      // argsort-order rank of each (dy,dx)

// ---- f32x2 helpers -------------------------------------------------------
__device__ __forceinline__ unsigned long long f2u(float a, float b) {
    unsigned long long r;
    asm("mov.b64 %0, {%1,%2};" : "=l"(r) : "f"(a), "f"(b));
    return r;
}
__device__ __forceinline__ float2 u2f(unsigned long long v) {
    float2 r;
    asm("mov.b64 {%0,%1}, %2;" : "=f"(r.x), "=f"(r.y) : "l"(v));
    return r;
}
__device__ __forceinline__ void fma2(unsigned long long& acc,
                                     unsigned long long a,
                                     unsigned long long b) {
    asm("fma.rn.f32x2 %0, %1, %2, %0;" : "+l"(acc) : "l"(a), "l"(b));
}
__device__ __forceinline__ float frcp(float x) {
    float r;
    asm("rcp.approx.ftz.f32 %0, %1;" : "=f"(r) : "f"(x));
    return r;
}

__device__ __forceinline__ float kc(int m, int dx) {   // kernel row value
    if (m < 0 || m > 40) return 0.f;
    int dy = m - 20;
    return 0.7f * expf(-sqrtf((float)(dx*dx + dy*dy)) * (1.9f/24.f));
}

// ---------------------------------------------------------------------------
// Kernel 0: bitmasks, 8 px/thread (2x LDG.128 per map), 1280 blocks
//           + fused LUT build (pair K-table + rank).
// ---------------------------------------------------------------------------
__global__ void __launch_bounds__(256) bitmask_kernel(
    const float4* __restrict__ src4, const float4* __restrict__ dst4,
    const float* __restrict__ xx,    const float* __restrict__ yy)
{
    int t    = blockIdx.x * 256 + threadIdx.x;    // NPIX/8 threads
    int sub  = threadIdx.x & 3;                   // 4 threads per mask word

    float4 s0 = src4[2*t], s1 = src4[2*t + 1];
    float4 d0 = dst4[2*t], d1 = dst4[2*t + 1];
    unsigned ns = (s0.x > 0.5f)        | ((s0.y > 0.5f) << 1) |
                  ((s0.z > 0.5f) << 2) | ((s0.w > 0.5f) << 3) |
                  ((s1.x > 0.5f) << 4) | ((s1.y > 0.5f) << 5) |
                  ((s1.z > 0.5f) << 6) | ((s1.w > 0.5f) << 7);
    unsigned nd = (d0.x > 0.5f)        | ((d0.y > 0.5f) << 1) |
                  ((d0.z > 0.5f) << 2) | ((d0.w > 0.5f) << 3) |
                  ((d1.x > 0.5f) << 4) | ((d1.y > 0.5f) << 5) |
                  ((d1.z > 0.5f) << 6) | ((d1.w > 0.5f) << 7);
    unsigned vs = ns << (sub * 8);
    unsigned vd = nd << (sub * 8);
    #pragma unroll
    for (int m = 1; m < 4; m <<= 1) {
        vs |= __shfl_xor_sync(0xFFFFFFFFu, vs, m);
        vd |= __shfl_xor_sync(0xFFFFFFFFu, vd, m);
    }
    if (sub == 0) { g_srcm[t >> 2] = vs; g_dstm[t >> 2] = vd; }

    if (blockIdx.x < 9) {                          // one-shot LUT build
        int i = blockIdx.x * 256 + threadIdx.x;
        if (i < KP2ROWS*41) {
            int mp = i / 41, dx = i % 41 - 20;
            g_K2[i] = make_float2(kc(mp - 7, dx), kc(mp - 8, dx));
        }
        if (i < 105) {
            int dx = (int)xx[i], dy = (int)yy[i];
            g_rank[(dy + 3)*15 + (dx + 7)] = i;    // exact argsort order
        }
    }
}

// ---------------------------------------------------------------------------
// 15/5-bit neighborhood window extraction from 3 mask words.
// ---------------------------------------------------------------------------
__device__ __forceinline__ unsigned win_extract(
    unsigned l, unsigned m, unsigned r, int j, int radius)
{
    if (j < 16) {
        unsigned long long lm = ((unsigned long long)m << 32) | l;
        return (unsigned)(lm >> (32 + j - radius));
    } else {
        unsigned long long mr = ((unsigned long long)r << 32) | m;
        return (unsigned)(mr >> (j - radius));
    }
}

// ---------------------------------------------------------------------------
// Kernel 1: sparsity filter + nearest-correspondence (bitmask windows).
// ---------------------------------------------------------------------------
__global__ void __launch_bounds__(256) match_kernel()
{
    __shared__ int s_rank[7*15];
    if (threadIdx.x < 105) s_rank[threadIdx.x] = g_rank[threadIdx.x];
    __syncthreads();

    int gid = blockIdx.x * 256 + threadIdx.x;
    int j   = gid & 31;
    int wi  = gid >> 5;

    unsigned own = g_srcm[wi];
    if (own == 0) {                          // early-out (~52% of warps)
        if (j == 0) g_mask[wi] = 0;
        return;
    }

    int wx  = wi & (WW - 1);
    int yb  = wi >> 5;
    int y   = yb % Hc;
    int b   = yb / Hc;

    unsigned sw[3][3];
    #pragma unroll
    for (int r = 0; r < 3; r++) {
        int ry = y - 2 + r;
        #pragma unroll
        for (int c = 0; c < 3; c++) {
            int rc = wx - 1 + c;
            unsigned v = 0;
            if ((unsigned)ry < (unsigned)Hc && (unsigned)rc < (unsigned)WW)
                v = g_srcm[(b*Hc + ry)*WW + rc];
            sw[r][c] = v;
        }
    }
    bool active = (own >> j) & 1u;
    unsigned h0 = win_extract(sw[0][0], sw[0][1], sw[0][2], j, 2) & 31u;
    unsigned h1 = win_extract(sw[1][0], sw[1][1], sw[1][2], j, 2) & 31u;
    unsigned h2 = win_extract(sw[2][0], sw[2][1], sw[2][2], j, 2) & 3u;
    bool kept = active && !(h0 | h1 | h2);

    bool found = false;
    float vx = 0.f, vy = 0.f;
    if (__ballot_sync(0xFFFFFFFFu, kept)) {
        int bestkey = 1 << 30, bdx = 0, bdy = 0;
        #pragma unroll
        for (int r = 0; r < 7; r++) {
            int dy = r - 3;
            int ry = y + dy;
            unsigned l = 0, m = 0, rr = 0;
            if ((unsigned)ry < (unsigned)Hc) {
                int base = (b*Hc + ry)*WW;
                if (wx > 0)      l  = g_dstm[base + wx - 1];
                m = g_dstm[base + wx];
                if (wx < WW - 1) rr = g_dstm[base + wx + 1];
            }
            if (kept) {
                unsigned win = win_extract(l, m, rr, j, 7) & 0x7FFFu;
                while (win) {
                    int k = __ffs(win) - 1; win &= win - 1;
                    int key = s_rank[r*15 + k];
                    if (key < bestkey) { bestkey = key; bdx = k - 7; bdy = dy; }
                }
            }
        }
        if (kept && bestkey < (1 << 30)) {
            found = true; vx = (float)bdx; vy = (float)bdy;
        }
    }

    unsigned fb = __ballot_sync(0xFFFFFFFFu, found);
    if (j == 0) g_mask[wi] = fb;
    if (found)  g_v[gid] = make_float2(vx, vy);
}

// ---------------------------------------------------------------------------
// Kernel 2: sparse splat-as-gather, 32x64 tile, 8 rows/thread,
// row-bucketed CSR, f32x2 packed taps, unroll-4 pipelined main loop,
// vectorized zero-fast epilogue.
// ---------------------------------------------------------------------------
__global__ void __launch_bounds__(256) splat_kernel(float* __restrict__ out)
{
    __shared__ float2   s_K2[KP2ROWS*41];
    __shared__ float4   s_pts[CAP];
    __shared__ int      s_rowcnt[HROWS];
    __shared__ int      s_rowofs[HROWS + 1];
    __shared__ unsigned s_tw[TLY];           // tile-row found words

    int tid  = threadIdx.x;
    int lane = tid & 31;
    int wrp  = tid >> 5;

    for (int i = tid; i < KP2ROWS*41; i += 256) s_K2[i] = g_K2[i];
    if (tid < HROWS) s_rowcnt[tid] = 0;

    int x0 = blockIdx.x * TLX;
    int y0 = blockIdx.y * TLY;
    int b  = blockIdx.z;
    __syncthreads();

    // Phase A: load halo mask words (104 rows x 3 words = 312), count per row.
    unsigned wrd[2]; int hrr[2], wjj[2], ofs[2];
    #pragma unroll
    for (int it = 0; it < 2; it++) {
        int t = tid + it*256;
        wrd[it] = 0; ofs[it] = 0; hrr[it] = 0; wjj[it] = 0;
        if (t < HROWS * 3) {
            int hr  = t / 3;
            int wi2 = t % 3 - 1;
            int ry  = y0 - 20 + hr;
            int wj  = (x0 >> 5) + wi2;
            hrr[it] = hr; wjj[it] = wj;
            if ((unsigned)ry < (unsigned)Hc && (unsigned)wj < (unsigned)WW) {
                unsigned w = g_mask[(b*Hc + ry)*WW + wj];
                if (wi2 == 0 && hr >= 20 && hr < 20 + TLY) s_tw[hr - 20] = w;
                if (wi2 == -1) w &= 0xFFFFF000u;   // keep x >= x0-20
                if (wi2 ==  1) w &= 0x000FFFFFu;   // keep x <= x0+51
                wrd[it] = w;
            }
            if (wrd[it]) ofs[it] = atomicAdd(&s_rowcnt[hr], __popc(wrd[it]));
        }
    }
    __syncthreads();

    // Phase B: exclusive prefix sum over 104 row counts (warp 0).
    if (wrp == 0) {
        int carry = 0;
        #pragma unroll
        for (int c = 0; c < 4; c++) {
            int idx  = c*32 + lane;
            int vcnt = (idx < HROWS) ? s_rowcnt[idx] : 0;
            int inc  = vcnt;
            #pragma unroll
            for (int d = 1; d < 32; d <<= 1) {
                int t2 = __shfl_up_sync(0xFFFFFFFFu, inc, d);
                if (lane >= d) inc += t2;
            }
            if (idx <= HROWS) s_rowofs[idx] = inc - vcnt + carry;
            carry += __shfl_sync(0xFFFFFFFFu, inc, 31);
        }
        if (lane == 0) s_rowofs[HROWS] = carry;
    }
    __syncthreads();

    // Phase C: write points bucketed by halo row.
    #pragma unroll
    for (int it = 0; it < 2; it++) {
        if (wrd[it]) {
            int slot = s_rowofs[hrr[it]] + ofs[it];
            int ry   = y0 - 20 + hrr[it];
            unsigned w2 = wrd[it];
            while (w2) {
                int jb = __ffs(w2) - 1; w2 &= w2 - 1;
                int px = (wjj[it] << 5) + jb;
                float2 v = g_v[(b*Hc + ry)*Wc + px];
                if (slot < CAP)
                    s_pts[slot] = make_float4(__int_as_float(px - x0 + 20),
                                              __int_as_float(hrr[it]),
                                              v.x, v.y);
                slot++;
            }
        }
    }
    __syncthreads();

    // Main loop: thread (g, tx) owns rows y0+8g..y0+8g+7 at column x0+tx.
    int tx = lane;
    int g8 = wrp * 8;
    int beg = min(s_rowofs[g8], CAP);
    int end = min(s_rowofs[min(g8 + 48, HROWS)], CAP);

    unsigned long long dd[4] = {0,0,0,0}, sxx[4] = {0,0,0,0}, syy[4] = {0,0,0,0};
    const unsigned long long ones = f2u(1.f, 1.f);

    #pragma unroll 4
    for (int i = beg; i < end; i++) {
        float4 p = s_pts[i];
        int u = __float_as_int(p.x) - tx;            // dx+20
        if ((unsigned)u <= 40u) {
            int base = (__float_as_int(p.y) - g8 + 7) * 41 + u;
            unsigned long long pz2 = f2u(p.z, p.z);
            unsigned long long pw2 = f2u(p.w, p.w);
            #pragma unroll
            for (int q = 0; q < 4; q++) {
                unsigned long long w =
                    *reinterpret_cast<const unsigned long long*>(&s_K2[base - 82*q]);
                fma2(dd[q],  w, ones);
                fma2(sxx[q], w, pz2);
                fma2(syy[q], w, pw2);
            }
        }
    }

    // Epilogue 1: morphed x/y (dense, per-column stores).
    int x = x0 + tx;
    float fx = (float)x;
    #pragma unroll
    for (int q = 0; q < 4; q++) {
        float2 dq = u2f(dd[q]), xq = u2f(sxx[q]), yq = u2f(syy[q]);
        float den[2] = {dq.x, dq.y}, sx[2] = {xq.x, xq.y}, sy[2] = {yq.x, yq.y};
        #pragma unroll
        for (int h = 0; h < 2; h++) {
            int tr  = g8 + 2*q + h;
            int y   = y0 + tr;
            int idx = (b*Hc + y)*Wc + x;
            float rcp = frcp(den[h] + 1.6f);
            out[idx]        = fx + sx[h] * rcp;         // morphedx
            out[NPIX + idx] = (float)y + sy[h] * rcp;   // morphedy
        }
    }

    // Epilogue 2: channels 2..5 with float4 stores + zero fast path.
    // lane -> (channel c = 2 + lane>>3, 4-px group grp = lane&7).
    {
        int c    = 2 + (lane >> 3);              // 2..5
        int grp  = lane & 7;
        int xg   = x0 + grp*4;
        bool usex = ((c & 1) == 0);              // ch2, ch4 use x-coord
        bool addv = (c >= 4);                    // ch4, ch5 add v
        float* obase = out + (size_t)c*NPIX + (b*Hc + (y0 + g8))*Wc + xg;
        int vbase = (b*Hc + (y0 + g8))*Wc + xg;
        #pragma unroll
        for (int rr = 0; rr < 8; rr++) {
            unsigned nib = (s_tw[g8 + rr] >> (grp*4)) & 0xFu;
            float4 val = make_float4(0.f, 0.f, 0.f, 0.f);
            if (nib) {
                float fy = (float)(y0 + g8 + rr);
                float vv[4];
                #pragma unroll
                for (int jj = 0; jj < 4; jj++) {
                    float r = 0.f;
                    if ((nib >> jj) & 1u) {
                        float base_c = usex ? (float)(xg + jj) : fy;
                        float add = 0.f;
                        if (addv) {
                            float2 gv = g_v[vbase + rr*Wc + jj];
                            add = usex ? gv.x : gv.y;
                        }
                        r = base_c + add;
                    }
                    vv[jj] = r;
                }
                val = make_float4(vv[0], vv[1], vv[2], vv[3]);
            }
            *reinterpret_cast<float4*>(obase + rr*Wc) = val;
        }
    }
}

extern "C" void kernel_launch(void* const* d_in, const int* in_sizes, int n_in,
                              void* d_out, int out_size)
{
    const float4* src4 = (const float4*)d_in[0];  // binMapsrc
    const float4* dst4 = (const float4*)d_in[1];  // binMapdst
    const float*  xx   = (const float*)d_in[2];
    const float*  yy   = (const float*)d_in[3];
    float* out = (float*)d_out;

    bitmask_kernel<<<NPIX/2048, 256>>>(src4, dst4, xx, yy);
    match_kernel<<<NPIX/256, 256>>>();

    dim3 grid(Wc/TLX, Hc/TLY, Bc);   // 32 x 5 x 8 = 1280 blocks
    splat_kernel<<<grid, 256>>>(out);

    (void)in_sizes; (void)n_in; (void)out_size;
}

// round 15
// speedup vs baseline: 1.2772x; 1.0159x over previous
#include <cuda_runtime.h>

#define Bc 8
#define Hc 320
#define Wc 1024
#define WW 32                    // 32-bit words per row
#define NPIX (Bc*Hc*Wc)          // 2621440
#define NWORD (NPIX/32)
#define TLX 32
#define TLY 64
#define CAP 512
#define HROWS 104                // halo rows per tile: [y0-20, y0+83]
#define KP2ROWS 55               // padded pair-table rows: mp in [0,54]

// Static device scratch (no allocations)
__device__ unsigned g_srcm[NWORD];
__device__ unsigned g_dstm[NWORD];
__device__ unsigned g_mask[NWORD];     // found bitmask
__device__ float2   g_v[NPIX];         // (vx,vy), sparse at found px
__device__ float2   g_K2[KP2ROWS*41];  // P2[mp] = (K[mp-7], K[mp-8])
__device__ int      g_rank[7*15];      // argsort-order rank of each (dy,dx)

// ---- f32x2 helpers -------------------------------------------------------
__device__ __forceinline__ unsigned long long f2u(float a, float b) {
    unsigned long long r;
    asm("mov.b64 %0, {%1,%2};" : "=l"(r) : "f"(a), "f"(b));
    return r;
}
__device__ __forceinline__ float2 u2f(unsigned long long v) {
    float2 r;
    asm("mov.b64 {%0,%1}, %2;" : "=f"(r.x), "=f"(r.y) : "l"(v));
    return r;
}
__device__ __forceinline__ void fma2(unsigned long long& acc,
                                     unsigned long long a,
                                     unsigned long long b) {
    asm("fma.rn.f32x2 %0, %1, %2, %0;" : "+l"(acc) : "l"(a), "l"(b));
}
__device__ __forceinline__ float frcp(float x) {
    float r;
    asm("rcp.approx.ftz.f32 %0, %1;" : "=f"(r) : "f"(x));
    return r;
}

__device__ __forceinline__ float kc(int m, int dx) {   // kernel row value
    if (m < 0 || m > 40) return 0.f;
    int dy = m - 20;
    return 0.7f * expf(-sqrtf((float)(dx*dx + dy*dy)) * (1.9f/24.f));
}

// ---------------------------------------------------------------------------
// Kernel 00: one-shot LUT build (pair K-table + rank). Separate launch:
// shifts the ncu -s5 capture slot for per-kernel attribution.
// ---------------------------------------------------------------------------
__global__ void __launch_bounds__(256) lut_kernel(
    const float* __restrict__ xx, const float* __restrict__ yy)
{
    int i = blockIdx.x * 256 + threadIdx.x;
    if (i < KP2ROWS*41) {
        int mp = i / 41, dx = i % 41 - 20;
        g_K2[i] = make_float2(kc(mp - 7, dx), kc(mp - 8, dx));
    }
    if (i < 105) {
        int dx = (int)xx[i], dy = (int)yy[i];
        g_rank[(dy + 3)*15 + (dx + 7)] = i;        // exact argsort order
    }
}

// ---------------------------------------------------------------------------
// Kernel 0: bitmasks, 8 px/thread (2x LDG.128 per map), 1280 blocks.
// ---------------------------------------------------------------------------
__global__ void __launch_bounds__(256) bitmask_kernel(
    const float4* __restrict__ src4, const float4* __restrict__ dst4)
{
    int t    = blockIdx.x * 256 + threadIdx.x;    // NPIX/8 threads
    int sub  = threadIdx.x & 3;                   // 4 threads per mask word

    float4 s0 = src4[2*t], s1 = src4[2*t + 1];
    float4 d0 = dst4[2*t], d1 = dst4[2*t + 1];
    unsigned ns = (s0.x > 0.5f)        | ((s0.y > 0.5f) << 1) |
                  ((s0.z > 0.5f) << 2) | ((s0.w > 0.5f) << 3) |
                  ((s1.x > 0.5f) << 4) | ((s1.y > 0.5f) << 5) |
                  ((s1.z > 0.5f) << 6) | ((s1.w > 0.5f) << 7);
    unsigned nd = (d0.x > 0.5f)        | ((d0.y > 0.5f) << 1) |
                  ((d0.z > 0.5f) << 2) | ((d0.w > 0.5f) << 3) |
                  ((d1.x > 0.5f) << 4) | ((d1.y > 0.5f) << 5) |
                  ((d1.z > 0.5f) << 6) | ((d1.w > 0.5f) << 7);
    unsigned vs = ns << (sub * 8);
    unsigned vd = nd << (sub * 8);
    #pragma unroll
    for (int m = 1; m < 4; m <<= 1) {
        vs |= __shfl_xor_sync(0xFFFFFFFFu, vs, m);
        vd |= __shfl_xor_sync(0xFFFFFFFFu, vd, m);
    }
    if (sub == 0) { g_srcm[t >> 2] = vs; g_dstm[t >> 2] = vd; }
}

// ---------------------------------------------------------------------------
// 15/5-bit neighborhood window extraction from 3 mask words.
// ---------------------------------------------------------------------------
__device__ __forceinline__ unsigned win_extract(
    unsigned l, unsigned m, unsigned r, int j, int radius)
{
    if (j < 16) {
        unsigned long long lm = ((unsigned long long)m << 32) | l;
        return (unsigned)(lm >> (32 + j - radius));
    } else {
        unsigned long long mr = ((unsigned long long)r << 32) | m;
        return (unsigned)(mr >> (j - radius));
    }
}

// ---------------------------------------------------------------------------
// Kernel 1: sparsity filter + nearest-correspondence (bitmask windows).
// No shared preamble / no barrier: early-out warps exit after ONE load.
// rank lookups go through __ldg (L2-hot, only at hit bits).
// ---------------------------------------------------------------------------
__global__ void __launch_bounds__(256) match_kernel()
{
    int gid = blockIdx.x * 256 + threadIdx.x;
    int j   = gid & 31;
    int wi  = gid >> 5;

    unsigned own = g_srcm[wi];
    if (own == 0) {                          // early-out (~52% of warps)
        if (j == 0) g_mask[wi] = 0;
        return;
    }

    int wx  = wi & (WW - 1);
    int yb  = wi >> 5;
    int y   = yb % Hc;
    int b   = yb / Hc;

    unsigned sw[3][3];
    #pragma unroll
    for (int r = 0; r < 3; r++) {
        int ry = y - 2 + r;
        #pragma unroll
        for (int c = 0; c < 3; c++) {
            int rc = wx - 1 + c;
            unsigned v = 0;
            if ((unsigned)ry < (unsigned)Hc && (unsigned)rc < (unsigned)WW)
                v = g_srcm[(b*Hc + ry)*WW + rc];
            sw[r][c] = v;
        }
    }
    bool active = (own >> j) & 1u;
    unsigned h0 = win_extract(sw[0][0], sw[0][1], sw[0][2], j, 2) & 31u;
    unsigned h1 = win_extract(sw[1][0], sw[1][1], sw[1][2], j, 2) & 31u;
    unsigned h2 = win_extract(sw[2][0], sw[2][1], sw[2][2], j, 2) & 3u;
    bool kept = active && !(h0 | h1 | h2);

    bool found = false;
    float vx = 0.f, vy = 0.f;
    if (__ballot_sync(0xFFFFFFFFu, kept)) {
        int bestkey = 1 << 30, bdx = 0, bdy = 0;
        #pragma unroll
        for (int r = 0; r < 7; r++) {
            int dy = r - 3;
            int ry = y + dy;
            unsigned l = 0, m = 0, rr = 0;
            if ((unsigned)ry < (unsigned)Hc) {
                int base = (b*Hc + ry)*WW;
                if (wx > 0)      l  = g_dstm[base + wx - 1];
                m = g_dstm[base + wx];
                if (wx < WW - 1) rr = g_dstm[base + wx + 1];
            }
            if (kept) {
                unsigned win = win_extract(l, m, rr, j, 7) & 0x7FFFu;
                while (win) {
                    int k = __ffs(win) - 1; win &= win - 1;
                    int key = __ldg(&g_rank[r*15 + k]);
                    if (key < bestkey) { bestkey = key; bdx = k - 7; bdy = dy; }
                }
            }
        }
        if (kept && bestkey < (1 << 30)) {
            found = true; vx = (float)bdx; vy = (float)bdy;
        }
    }

    unsigned fb = __ballot_sync(0xFFFFFFFFu, found);
    if (j == 0) g_mask[wi] = fb;
    if (found)  g_v[gid] = make_float2(vx, vy);
}

// ---------------------------------------------------------------------------
// Kernel 2: sparse splat-as-gather, 32x64 tile, 8 rows/thread,
// row-bucketed CSR, f32x2 packed taps, unroll-4 main loop,
// vectorized zero-fast epilogue. CAP=512 -> 8 blocks/SM.
// ---------------------------------------------------------------------------
__global__ void __launch_bounds__(256) splat_kernel(float* __restrict__ out)
{
    __shared__ float2   s_K2[KP2ROWS*41];
    __shared__ float4   s_pts[CAP];
    __shared__ int      s_rowcnt[HROWS];
    __shared__ int      s_rowofs[HROWS + 1];
    __shared__ unsigned s_tw[TLY];           // tile-row found words

    int tid  = threadIdx.x;
    int lane = tid & 31;
    int wrp  = tid >> 5;

    for (int i = tid; i < KP2ROWS*41; i += 256) s_K2[i] = g_K2[i];
    if (tid < HROWS) s_rowcnt[tid] = 0;

    int x0 = blockIdx.x * TLX;
    int y0 = blockIdx.y * TLY;
    int b  = blockIdx.z;
    __syncthreads();

    // Phase A: load halo mask words (104 rows x 3 words = 312), count per row.
    unsigned wrd[2]; int hrr[2], wjj[2], ofs[2];
    #pragma unroll
    for (int it = 0; it < 2; it++) {
        int t = tid + it*256;
        wrd[it] = 0; ofs[it] = 0; hrr[it] = 0; wjj[it] = 0;
        if (t < HROWS * 3) {
            int hr  = t / 3;
            int wi2 = t % 3 - 1;
            int ry  = y0 - 20 + hr;
            int wj  = (x0 >> 5) + wi2;
            hrr[it] = hr; wjj[it] = wj;
            if ((unsigned)ry < (unsigned)Hc && (unsigned)wj < (unsigned)WW) {
                unsigned w = g_mask[(b*Hc + ry)*WW + wj];
                if (wi2 == 0 && hr >= 20 && hr < 20 + TLY) s_tw[hr - 20] = w;
                if (wi2 == -1) w &= 0xFFFFF000u;   // keep x >= x0-20
                if (wi2 ==  1) w &= 0x000FFFFFu;   // keep x <= x0+51
                wrd[it] = w;
            }
            if (wrd[it]) ofs[it] = atomicAdd(&s_rowcnt[hr], __popc(wrd[it]));
        }
    }
    __syncthreads();

    // Phase B: exclusive prefix sum over 104 row counts (warp 0).
    if (wrp == 0) {
        int carry = 0;
        #pragma unroll
        for (int c = 0; c < 4; c++) {
            int idx  = c*32 + lane;
            int vcnt = (idx < HROWS) ? s_rowcnt[idx] : 0;
            int inc  = vcnt;
            #pragma unroll
            for (int d = 1; d < 32; d <<= 1) {
                int t2 = __shfl_up_sync(0xFFFFFFFFu, inc, d);
                if (lane >= d) inc += t2;
            }
            if (idx <= HROWS) s_rowofs[idx] = inc - vcnt + carry;
            carry += __shfl_sync(0xFFFFFFFFu, inc, 31);
        }
        if (lane == 0) s_rowofs[HROWS] = carry;
    }
    __syncthreads();

    // Phase C: write points bucketed by halo row.
    #pragma unroll
    for (int it = 0; it < 2; it++) {
        if (wrd[it]) {
            int slot = s_rowofs[hrr[it]] + ofs[it];
            int ry   = y0 - 20 + hrr[it];
            unsigned w2 = wrd[it];
            while (w2) {
                int jb = __ffs(w2) - 1; w2 &= w2 - 1;
                int px = (wjj[it] << 5) + jb;
                float2 v = g_v[(b*Hc + ry)*Wc + px];
                if (slot < CAP)
                    s_pts[slot] = make_float4(__int_as_float(px - x0 + 20),
                                              __int_as_float(hrr[it]),
                                              v.x, v.y);
                slot++;
            }
        }
    }
    __syncthreads();

    // Main loop: thread (g, tx) owns rows y0+8g..y0+8g+7 at column x0+tx.
    int tx = lane;
    int g8 = wrp * 8;
    int beg = min(s_rowofs[g8], CAP);
    int end = min(s_rowofs[min(g8 + 48, HROWS)], CAP);

    unsigned long long dd[4] = {0,0,0,0}, sxx[4] = {0,0,0,0}, syy[4] = {0,0,0,0};
    const unsigned long long ones = f2u(1.f, 1.f);

    #pragma unroll 4
    for (int i = beg; i < end; i++) {
        float4 p = s_pts[i];
        int u = __float_as_int(p.x) - tx;            // dx+20
        if ((unsigned)u <= 40u) {
            int base = (__float_as_int(p.y) - g8 + 7) * 41 + u;
            unsigned long long pz2 = f2u(p.z, p.z);
            unsigned long long pw2 = f2u(p.w, p.w);
            #pragma unroll
            for (int q = 0; q < 4; q++) {
                unsigned long long w =
                    *reinterpret_cast<const unsigned long long*>(&s_K2[base - 82*q]);
                fma2(dd[q],  w, ones);
                fma2(sxx[q], w, pz2);
                fma2(syy[q], w, pw2);
            }
        }
    }

    // Epilogue 1: morphed x/y (dense, per-column stores).
    int x = x0 + tx;
    float fx = (float)x;
    #pragma unroll
    for (int q = 0; q < 4; q++) {
        float2 dq = u2f(dd[q]), xq = u2f(sxx[q]), yq = u2f(syy[q]);
        float den[2] = {dq.x, dq.y}, sx[2] = {xq.x, xq.y}, sy[2] = {yq.x, yq.y};
        #pragma unroll
        for (int h = 0; h < 2; h++) {
            int tr  = g8 + 2*q + h;
            int y   = y0 + tr;
            int idx = (b*Hc + y)*Wc + x;
            float rcp = frcp(den[h] + 1.6f);
            out[idx]        = fx + sx[h] * rcp;         // morphedx
            out[NPIX + idx] = (float)y + sy[h] * rcp;   // morphedy
        }
    }

    // Epilogue 2: channels 2..5 with float4 stores + zero fast path.
    {
        int c    = 2 + (lane >> 3);              // 2..5
        int grp  = lane & 7;
        int xg   = x0 + grp*4;
        bool usex = ((c & 1) == 0);              // ch2, ch4 use x-coord
        bool addv = (c >= 4);                    // ch4, ch5 add v
        float* obase = out + (size_t)c*NPIX + (b*Hc + (y0 + g8))*Wc + xg;
        int vbase = (b*Hc + (y0 + g8))*Wc + xg;
        #pragma unroll
        for (int rr = 0; rr < 8; rr++) {
            unsigned nib = (s_tw[g8 + rr] >> (grp*4)) & 0xFu;
            float4 val = make_float4(0.f, 0.f, 0.f, 0.f);
            if (nib) {
                float fy = (float)(y0 + g8 + rr);
                float vv[4];
                #pragma unroll
                for (int jj = 0; jj < 4; jj++) {
                    float r = 0.f;
                    if ((nib >> jj) & 1u) {
                        float base_c = usex ? (float)(xg + jj) : fy;
                        float add = 0.f;
                        if (addv) {
                            float2 gv = g_v[vbase + rr*Wc + jj];
                            add = usex ? gv.x : gv.y;
                        }
                        r = base_c + add;
                    }
                    vv[jj] = r;
                }
                val = make_float4(vv[0], vv[1], vv[2], vv[3]);
            }
            *reinterpret_cast<float4*>(obase + rr*Wc) = val;
        }
    }
}

extern "C" void kernel_launch(void* const* d_in, const int* in_sizes, int n_in,
                              void* d_out, int out_size)
{
    const float4* src4 = (const float4*)d_in[0];  // binMapsrc
    const float4* dst4 = (const float4*)d_in[1];  // binMapdst
    const float*  xx   = (const float*)d_in[2];
    const float*  yy   = (const float*)d_in[3];
    float* out = (float*)d_out;

    lut_kernel<<<9, 256>>>(xx, yy);
    bitmask_kernel<<<NPIX/2048, 256>>>(src4, dst4);
    match_kernel<<<NPIX/256, 256>>>();

    dim3 grid(Wc/TLX, Hc/TLY, Bc);   // 32 x 5 x 8 = 1280 blocks
    splat_kernel<<<grid, 256>>>(out);

    (void)in_sizes; (void)n_in; (void)out_size;
}